// round 13
// baseline (speedup 1.0000x reference)
#include <cuda_runtime.h>
#include <cuda_fp16.h>
#include <cstdint>

#define Bsz     32768
#define Dd      1024
#define Cc      40
#define CT      80            // 40 fwd + 40 rev output columns
#define RB      128           // rows (M) per CTA -> 256 CTAs
#define THREADS 256           // 8 warps: 4 M-warps x 2 N-warps
#define KC      32            // k per chunk
#define NCH     (Dd / KC)     // 32

#define AROWB   80            // fp16 row bytes (64 data + 16 pad) - LDSM conflict-free
#define AST_B   (RB * AROWB)              // 10240 per A stage
#define B_STAGE_B (CT * AROWB)            // 6400 per B stage
#define OFF_A0  1024
#define OFF_B0  (OFF_A0 + 4 * AST_B)           // 41984
#define SMEM_BYTES (OFF_B0 + 4 * B_STAGE_B)    // 67584

// epilogue overlay (aliases rings after mainloop)
#define BROW    81
#define EPI_BASE_F 256
#define EPI_WT_F   (EPI_BASE_F + RB * BROW)
#define EPI_BB_F   (EPI_WT_F + 2 * Cc * Cc)

__device__ __half Wh[CT * Dd];   // fp16 copy of GEMM part of [W;W_rev]

extern __shared__ float smf[];

__device__ __forceinline__ uint32_t pk(float lo, float hi) {
    uint32_t r;
    asm("cvt.rn.f16x2.f32 %0, %1, %2;" : "=r"(r) : "f"(hi), "f"(lo));
    return r;
}

__device__ __forceinline__ void mma_16x8x16(float* d, const uint32_t* a,
                                            const uint32_t* bf) {
    asm volatile(
        "mma.sync.aligned.m16n8k16.row.col.f32.f16.f16.f32 "
        "{%0,%1,%2,%3}, {%4,%5,%6,%7}, {%8,%9}, {%0,%1,%2,%3};"
        : "+f"(d[0]), "+f"(d[1]), "+f"(d[2]), "+f"(d[3])
        : "r"(a[0]), "r"(a[1]), "r"(a[2]), "r"(a[3]), "r"(bf[0]), "r"(bf[1]));
}

__device__ __forceinline__ void ldsm4(uint32_t* r, uint32_t a) {
    asm volatile("ldmatrix.sync.aligned.m8n8.x4.shared.b16 {%0,%1,%2,%3}, [%4];"
                 : "=r"(r[0]), "=r"(r[1]), "=r"(r[2]), "=r"(r[3]) : "r"(a));
}
__device__ __forceinline__ void ldsm2(uint32_t* r, uint32_t a) {
    asm volatile("ldmatrix.sync.aligned.m8n8.x2.shared.b16 {%0,%1}, [%2];"
                 : "=r"(r[0]), "=r"(r[1]) : "r"(a));
}

__global__ void convert_w(const float* __restrict__ W,
                          const float* __restrict__ Wr) {
    const int idx = blockIdx.x * 256 + threadIdx.x;
    if (idx < CT * Dd) {
        const int r = idx >> 10, k = idx & 1023;
        const float* Wp = (r < Cc) ? W  + (size_t)r        * (Dd + Cc)
                                   : Wr + (size_t)(r - Cc) * (Dd + Cc);
        Wh[idx] = __float2half_rn(Wp[k]);
    }
}

__global__ void __launch_bounds__(THREADS, 2)
bichain_r13(const float* __restrict__ src,
            const float* __restrict__ W,  const float* __restrict__ b,
            const float* __restrict__ Wr, const float* __restrict__ br,
            float* __restrict__ out) {
    const int tid  = threadIdx.x;
    const int warp = tid >> 5;
    const int lane = tid & 31;
    const int row0 = blockIdx.x * RB;

    uint32_t smb;
    asm("{ .reg .u64 t; cvta.to.shared.u64 t, %1; cvt.u32.u64 %0, t; }"
        : "=r"(smb) : "l"(smf));

    // ---- producer A: LDG fp32 (reg-staged) -> cvt -> STS fp16 ----
    // row = tid>>1 (16 rows/warp -> optimal 128B-line wavefronts), half = tid&1
    const int prow = tid >> 1, phalf = tid & 1;
    const float4* gAbase =
        (const float4*)(src + (size_t)(row0 + prow) * Dd + phalf * 16);
    const uint32_t stsoff = (uint32_t)(prow * AROWB + phalf * 32);

    auto ldgA = [&](int ch, float4 (&S)[4]) {
        const float4* p = gAbase + ch * (KC / 4);
        S[0] = p[0]; S[1] = p[1]; S[2] = p[2]; S[3] = p[3];
    };
    auto stsA = [&](const float4 (&S)[4], uint32_t sbase) {
        uint32_t q0 = pk(S[0].x, S[0].y), q1 = pk(S[0].z, S[0].w);
        uint32_t q2 = pk(S[1].x, S[1].y), q3 = pk(S[1].z, S[1].w);
        uint32_t q4 = pk(S[2].x, S[2].y), q5 = pk(S[2].z, S[2].w);
        uint32_t q6 = pk(S[3].x, S[3].y), q7 = pk(S[3].z, S[3].w);
        asm volatile("st.shared.v4.b32 [%0], {%1,%2,%3,%4};"
                     :: "r"(sbase + stsoff), "r"(q0), "r"(q1), "r"(q2), "r"(q3));
        asm volatile("st.shared.v4.b32 [%0], {%1,%2,%3,%4};"
                     :: "r"(sbase + stsoff + 16), "r"(q4), "r"(q5), "r"(q6), "r"(q7));
    };

    // ---- producer B: cp.async ring-4, B-only groups (identical data path to R12) ----
    const int brow = tid >> 2, bseg = tid & 3;
    const __half* gB0 = Wh + (size_t)brow * Dd + bseg * 8;
    const __half* gB1 = Wh + (size_t)(brow + 64) * Dd + bseg * 8;
    const uint32_t dB0 = (uint32_t)(brow * AROWB + bseg * 16);
    const uint32_t dB1 = (uint32_t)((brow + 64) * AROWB + bseg * 16);

    auto cpB = [&](int ch) {
        if (ch < NCH) {
            const uint32_t bS = smb + OFF_B0 + (uint32_t)(ch & 3) * B_STAGE_B;
            const int k0 = ch * KC;
            asm volatile("cp.async.ca.shared.global [%0], [%1], 16;"
                         :: "r"(bS + dB0), "l"(gB0 + k0));
            if (tid < 64)
                asm volatile("cp.async.ca.shared.global [%0], [%1], 16;"
                             :: "r"(bS + dB1), "l"(gB1 + k0));
        }
        asm volatile("cp.async.commit_group;");   // uniform accounting
    };

    // ---- consumer offsets (A: R8-verified ldmatrix map; B: R12 verbatim) ----
    const int mw = warp >> 1, nw = warp & 1;
    const int qr = lane >> 2, qc = lane & 3;
    const int g8 = lane >> 3, i8 = lane & 7;

    uint32_t aoff[2][2];
    #pragma unroll
    for (int mt = 0; mt < 2; ++mt)
        #pragma unroll
        for (int kk = 0; kk < 2; ++kk)
            aoff[mt][kk] = (uint32_t)((mw * 32 + mt * 16 + (g8 & 1) * 8 + i8) * AROWB
                                      + (g8 >> 1) * 16 + kk * 32);
    uint32_t boff[2][2], boffc[2];
    #pragma unroll
    for (int p = 0; p < 2; ++p)
        #pragma unroll
        for (int kk = 0; kk < 2; ++kk)
            boff[p][kk] = (uint32_t)((nw * 40 + p * 16 + (g8 >> 1) * 8 + i8) * AROWB
                                     + (g8 & 1) * 16 + kk * 32);
    {
        const int l2g = (lane & 15) >> 3;
        #pragma unroll
        for (int kk = 0; kk < 2; ++kk)
            boffc[kk] = (uint32_t)((nw * 40 + 32 + i8) * AROWB + l2g * 16 + kk * 32);
    }

    float acc[2][5][4];
    #pragma unroll
    for (int mt = 0; mt < 2; ++mt)
        #pragma unroll
        for (int t = 0; t < 5; ++t)
            #pragma unroll
            for (int e = 0; e < 4; ++e) acc[mt][t][e] = 0.f;

    float4 setA[4], setB[4];   // parity register stages (no copies: loop unrolled x2)

    // ---- prologue ----
    ldgA(0, setA);
    cpB(0); cpB(1); cpB(2);
    stsA(setA, smb + OFF_A0);          // A(0) -> stage 0 (stalls on LDG(0); prologue only)
    ldgA(1, setB);                     // consumed (STS) at iter 0
    ldgA(2, setA);                     // consumed at iter 1
    __syncthreads();

    auto step = [&](int ch, float4 (&S)[4]) {
        // pending B groups {ch, ch+1, ch+2} -> release when B(ch) lands
        asm volatile("cp.async.wait_group 2;");
        __syncthreads();               // prev stages consumed; A(ch) STS visible
        if (ch + 1 < NCH) stsA(S, smb + OFF_A0 + (uint32_t)((ch + 1) & 3) * AST_B);
        if (ch + 3 < NCH) ldgA(ch + 3, S);    // 2 bodies of slack before its STS
        cpB(ch + 3);

        const uint32_t sbA = smb + OFF_A0 + (uint32_t)(ch & 3) * AST_B;
        const uint32_t sbB = smb + OFF_B0 + (uint32_t)(ch & 3) * B_STAGE_B;
        #pragma unroll
        for (int kk = 0; kk < 2; ++kk) {
            uint32_t a0[4], a1[4], q0[4], q1[4], q2[2];
            ldsm4(a0, sbA + aoff[0][kk]);
            ldsm4(a1, sbA + aoff[1][kk]);
            ldsm4(q0, sbB + boff[0][kk]);
            ldsm4(q1, sbB + boff[1][kk]);
            ldsm2(q2, sbB + boffc[kk]);
            mma_16x8x16(acc[0][0], a0, q0);
            mma_16x8x16(acc[0][1], a0, q0 + 2);
            mma_16x8x16(acc[0][2], a0, q1);
            mma_16x8x16(acc[0][3], a0, q1 + 2);
            mma_16x8x16(acc[0][4], a0, q2);
            mma_16x8x16(acc[1][0], a1, q0);
            mma_16x8x16(acc[1][1], a1, q0 + 2);
            mma_16x8x16(acc[1][2], a1, q1);
            mma_16x8x16(acc[1][3], a1, q1 + 2);
            mma_16x8x16(acc[1][4], a1, q2);
        }
    };

    for (int ch = 0; ch < NCH; ch += 2) {
        step(ch,     setB);    // STS A(ch+1) from setB, LDG A(ch+3) into setB
        step(ch + 1, setA);    // STS A(ch+2) from setA, LDG A(ch+4) into setA
    }
    __syncthreads();   // all stages consumed before overlay writes

    // ---- epilogue: prefetch chain weights into regs FIRST (overlaps writeback) ----
    float wreg[13];
    int   widx[13];
    #pragma unroll
    for (int k = 0; k < 13; ++k) {
        const int idx = tid + k * THREADS;
        widx[k] = idx;
        if (idx < 2 * Cc * Cc) {
            const int chn = idx / (Cc * Cc);
            const int rem = idx - chn * Cc * Cc;
            const int i = rem / Cc, j = rem - i * Cc;
            const float* Wp = chn ? Wr : W;
            wreg[k] = Wp[(size_t)i * (Dd + Cc) + Dd + j];
        }
    }
    float breg = 0.f;
    if (tid < 2 * Cc) breg = (tid < Cc) ? b[tid] : br[tid - Cc];

    // ---- accumulators -> smem bases[128][81] ----
    float* bases = smf + EPI_BASE_F;
    #pragma unroll
    for (int mt = 0; mt < 2; ++mt) {
        const int r = mw * 32 + mt * 16 + qr;
        #pragma unroll
        for (int t = 0; t < 5; ++t) {
            const int c = nw * 40 + t * 8 + qc * 2;
            bases[(r    ) * BROW + c    ] = acc[mt][t][0];
            bases[(r    ) * BROW + c + 1] = acc[mt][t][1];
            bases[(r + 8) * BROW + c    ] = acc[mt][t][2];
            bases[(r + 8) * BROW + c + 1] = acc[mt][t][3];
        }
    }

    float* wt = smf + EPI_WT_F;
    float* bb = smf + EPI_BB_F;
    #pragma unroll
    for (int k = 0; k < 13; ++k)
        if (widx[k] < 2 * Cc * Cc) wt[widx[k]] = wreg[k];
    if (tid < 2 * Cc) bb[tid] = breg;
    __syncthreads();

    // ---- sequential chains: 256 threads = 128 rows x 2 chains (split partials) ----
    {
        const int row = tid >> 1, chn = tid & 1;
        float* my        = bases + row * BROW + chn * Cc;
        const float* wtc = wt + chn * Cc * Cc;
        const float* bbc = bb + chn * Cc;
        float s[Cc];
        #pragma unroll
        for (int i = 0; i < Cc; ++i) {
            float x0 = my[i] + bbc[i];
            float x1 = 0.f;
            #pragma unroll
            for (int j = 0; j + 1 < i; j += 2) {
                x0 = fmaf(s[j],     wtc[i * Cc + j],     x0);
                x1 = fmaf(s[j + 1], wtc[i * Cc + j + 1], x1);
            }
            if (i & 1) x0 = fmaf(s[i - 1], wtc[i * Cc + i - 1], x0);
            const float x = x0 + x1;
            s[i] = 1.0f / (1.0f + __expf(-x));
            my[i] = s[i];
        }
    }
    __syncthreads();

    // ---- combine fwd + reversed rev, coalesced store ----
    #pragma unroll
    for (int it = 0; it < (RB * Cc) / THREADS; ++it) {   // 20
        const int idx = tid + it * THREADS;
        const int r = idx / Cc, c = idx - r * Cc;
        const float vf = bases[r * BROW + c];
        const float vr = bases[r * BROW + Cc + (Cc - 1 - c)];
        out[(size_t)(row0 + r) * Cc + c] = 0.5f * (vf + vr);
    }
}

extern "C" void kernel_launch(void* const* d_in, const int* in_sizes, int n_in,
                              void* d_out, int out_size) {
    const float* src = (const float*)d_in[0];
    // d_in[1] = attn_mask (unused)
    const float* W   = (const float*)d_in[2];
    const float* b   = (const float*)d_in[3];
    const float* Wr  = (const float*)d_in[4];
    const float* br  = (const float*)d_in[5];
    float* out = (float*)d_out;

    convert_w<<<(CT * Dd + 255) / 256, 256>>>(W, Wr);
    cudaFuncSetAttribute(bichain_r13,
                         cudaFuncAttributeMaxDynamicSharedMemorySize, SMEM_BYTES);
    bichain_r13<<<Bsz / RB, THREADS, SMEM_BYTES>>>(src, W, b, Wr, br, out);
}

// round 14
// speedup vs baseline: 1.1714x; 1.1714x over previous
#include <cuda_runtime.h>
#include <cuda_fp16.h>
#include <cstdint>

#define Bsz     32768
#define Dd      1024
#define Cc      40
#define CT      80            // 40 fwd + 40 rev output columns
#define RB      128           // rows (M) per CTA -> 256 CTAs
#define THREADS 256           // 8 warps: 4 M-warps x 2 N-warps
#define KC      32            // k per chunk
#define NCH     (Dd / KC)     // 32

#define AROWB   80            // fp16 row bytes (64 data + 16 pad) - LDSM conflict-free
#define AST_B   (RB * AROWB)              // 10240 per A stage
#define B_STAGE_B (CT * AROWB)            // 6400 per B stage
#define OFF_A0  1024
#define OFF_B0  (OFF_A0 + 4 * AST_B)           // 41984
#define SMEM_BYTES (OFF_B0 + 4 * B_STAGE_B)    // 67584 -> 2 CTAs/SM

// epilogue overlay (aliases rings after mainloop)
#define BROW    81
#define EPI_BASE_F 256
#define EPI_WT_F   (EPI_BASE_F + RB * BROW)
#define EPI_BB_F   (EPI_WT_F + 2 * Cc * Cc)

__device__ __half Wh[CT * Dd];   // fp16 copy of GEMM part of [W;W_rev]

extern __shared__ float smf[];

__device__ __forceinline__ uint32_t pk(float lo, float hi) {
    uint32_t r;
    asm("cvt.rn.f16x2.f32 %0, %1, %2;" : "=r"(r) : "f"(hi), "f"(lo));
    return r;
}

__device__ __forceinline__ void mma_16x8x16(float* d, const uint32_t* a,
                                            const uint32_t* bf) {
    asm volatile(
        "mma.sync.aligned.m16n8k16.row.col.f32.f16.f16.f32 "
        "{%0,%1,%2,%3}, {%4,%5,%6,%7}, {%8,%9}, {%0,%1,%2,%3};"
        : "+f"(d[0]), "+f"(d[1]), "+f"(d[2]), "+f"(d[3])
        : "r"(a[0]), "r"(a[1]), "r"(a[2]), "r"(a[3]), "r"(bf[0]), "r"(bf[1]));
}

__device__ __forceinline__ void ldsm4(uint32_t* r, uint32_t a) {
    asm volatile("ldmatrix.sync.aligned.m8n8.x4.shared.b16 {%0,%1,%2,%3}, [%4];"
                 : "=r"(r[0]), "=r"(r[1]), "=r"(r[2]), "=r"(r[3]) : "r"(a));
}
__device__ __forceinline__ void ldsm2(uint32_t* r, uint32_t a) {
    asm volatile("ldmatrix.sync.aligned.m8n8.x2.shared.b16 {%0,%1}, [%2];"
                 : "=r"(r[0]), "=r"(r[1]) : "r"(a));
}

__global__ void convert_w(const float* __restrict__ W,
                          const float* __restrict__ Wr) {
    const int idx = blockIdx.x * 256 + threadIdx.x;
    if (idx < CT * Dd) {
        const int r = idx >> 10, k = idx & 1023;
        const float* Wp = (r < Cc) ? W  + (size_t)r        * (Dd + Cc)
                                   : Wr + (size_t)(r - Cc) * (Dd + Cc);
        Wh[idx] = __float2half_rn(Wp[k]);
    }
}

__global__ void __launch_bounds__(THREADS, 2)
bichain_r14(const float* __restrict__ src,
            const float* __restrict__ W,  const float* __restrict__ b,
            const float* __restrict__ Wr, const float* __restrict__ br,
            float* __restrict__ out) {
    const int tid  = threadIdx.x;
    const int warp = tid >> 5;
    const int lane = tid & 31;
    const int row0 = blockIdx.x * RB;

    uint32_t smb;
    asm("{ .reg .u64 t; cvta.to.shared.u64 t, %1; cvt.u32.u64 %0, t; }"
        : "=r"(smb) : "l"(smf));

    // ---- producer A: LDG.128 (coalesced: 8 lanes/row -> 4 lines/warp-op) ----
    const int arow = tid >> 3, aseg = tid & 7;
    const float4* gA[4];
    uint32_t dsts[4];
    #pragma unroll
    for (int i = 0; i < 4; ++i) {
        gA[i]   = (const float4*)(src + (size_t)(row0 + arow + 32 * i) * Dd
                                  + aseg * 4);
        dsts[i] = (uint32_t)((arow + 32 * i) * AROWB + aseg * 8);
    }
    auto ldgA = [&](int ch, float4 (&S)[4]) {
        #pragma unroll
        for (int i = 0; i < 4; ++i) S[i] = gA[i][ch * (KC / 4)];
    };
    auto stsA = [&](const float4 (&S)[4], uint32_t sbase) {
        #pragma unroll
        for (int i = 0; i < 4; ++i) {
            uint32_t q0 = pk(S[i].x, S[i].y), q1 = pk(S[i].z, S[i].w);
            asm volatile("st.shared.v2.b32 [%0], {%1,%2};"
                         :: "r"(sbase + dsts[i]), "r"(q0), "r"(q1));
        }
    };

    // ---- producer B: cp.async ring-4, B-only groups (R12 data path) ----
    const int brow = tid >> 2, bseg = tid & 3;
    const __half* gB0 = Wh + (size_t)brow * Dd + bseg * 8;
    const __half* gB1 = Wh + (size_t)(brow + 64) * Dd + bseg * 8;
    const uint32_t dB0 = (uint32_t)(brow * AROWB + bseg * 16);
    const uint32_t dB1 = (uint32_t)((brow + 64) * AROWB + bseg * 16);

    auto cpB = [&](int ch) {
        if (ch < NCH) {
            const uint32_t bS = smb + OFF_B0 + (uint32_t)(ch & 3) * B_STAGE_B;
            const int k0 = ch * KC;
            asm volatile("cp.async.ca.shared.global [%0], [%1], 16;"
                         :: "r"(bS + dB0), "l"(gB0 + k0));
            if (tid < 64)
                asm volatile("cp.async.ca.shared.global [%0], [%1], 16;"
                             :: "r"(bS + dB1), "l"(gB1 + k0));
        }
        asm volatile("cp.async.commit_group;");   // uniform accounting
    };

    // ---- consumer offsets (A: R8/R13-verified ldmatrix map; B: R12 verbatim) ----
    const int mw = warp >> 1, nw = warp & 1;
    const int qr = lane >> 2, qc = lane & 3;
    const int g8 = lane >> 3, i8 = lane & 7;

    uint32_t aoff[2][2];
    #pragma unroll
    for (int mt = 0; mt < 2; ++mt)
        #pragma unroll
        for (int kk = 0; kk < 2; ++kk)
            aoff[mt][kk] = (uint32_t)((mw * 32 + mt * 16 + (g8 & 1) * 8 + i8) * AROWB
                                      + (g8 >> 1) * 16 + kk * 32);
    uint32_t boff[2][2], boffc[2];
    #pragma unroll
    for (int p = 0; p < 2; ++p)
        #pragma unroll
        for (int kk = 0; kk < 2; ++kk)
            boff[p][kk] = (uint32_t)((nw * 40 + p * 16 + (g8 >> 1) * 8 + i8) * AROWB
                                     + (g8 & 1) * 16 + kk * 32);
    {
        const int l2g = (lane & 15) >> 3;
        #pragma unroll
        for (int kk = 0; kk < 2; ++kk)
            boffc[kk] = (uint32_t)((nw * 40 + 32 + i8) * AROWB + l2g * 16 + kk * 32);
    }

    float acc[2][5][4];
    #pragma unroll
    for (int mt = 0; mt < 2; ++mt)
        #pragma unroll
        for (int t = 0; t < 5; ++t)
            #pragma unroll
            for (int e = 0; e < 4; ++e) acc[mt][t][e] = 0.f;

    float4 setA[4], setB[4];   // parity register stages (loop unrolled x2, no copies)

    // ---- prologue ----
    ldgA(0, setA);
    cpB(0); cpB(1); cpB(2);
    stsA(setA, smb + OFF_A0);          // A(0) -> stage 0
    ldgA(1, setB);                     // STS'd at iter 0
    ldgA(2, setA);                     // STS'd at iter 1
    __syncthreads();

    auto step = [&](int ch, float4 (&S)[4]) {
        // pending B groups {ch, ch+1, ch+2} -> release when B(ch) lands
        asm volatile("cp.async.wait_group 2;");
        __syncthreads();               // prev stages consumed; A(ch) STS visible
        if (ch + 1 < NCH) stsA(S, smb + OFF_A0 + (uint32_t)((ch + 1) & 3) * AST_B);
        if (ch + 3 < NCH) ldgA(ch + 3, S);    // 2 bodies of slack before its STS
        cpB(ch + 3);

        const uint32_t sbA = smb + OFF_A0 + (uint32_t)(ch & 3) * AST_B;
        const uint32_t sbB = smb + OFF_B0 + (uint32_t)(ch & 3) * B_STAGE_B;
        #pragma unroll
        for (int kk = 0; kk < 2; ++kk) {
            uint32_t a0[4], a1[4], q0[4], q1[4], q2[2];
            ldsm4(a0, sbA + aoff[0][kk]);
            ldsm4(a1, sbA + aoff[1][kk]);
            ldsm4(q0, sbB + boff[0][kk]);
            ldsm4(q1, sbB + boff[1][kk]);
            ldsm2(q2, sbB + boffc[kk]);
            mma_16x8x16(acc[0][0], a0, q0);
            mma_16x8x16(acc[0][1], a0, q0 + 2);
            mma_16x8x16(acc[0][2], a0, q1);
            mma_16x8x16(acc[0][3], a0, q1 + 2);
            mma_16x8x16(acc[0][4], a0, q2);
            mma_16x8x16(acc[1][0], a1, q0);
            mma_16x8x16(acc[1][1], a1, q0 + 2);
            mma_16x8x16(acc[1][2], a1, q1);
            mma_16x8x16(acc[1][3], a1, q1 + 2);
            mma_16x8x16(acc[1][4], a1, q2);
        }
    };

    for (int ch = 0; ch < NCH; ch += 2) {
        step(ch,     setB);    // STS A(ch+1) from setB, LDG A(ch+3) into setB
        step(ch + 1, setA);    // STS A(ch+2) from setA, LDG A(ch+4) into setA
    }
    __syncthreads();   // all stages consumed before overlay writes

    // ---- epilogue: prefetch chain weights into regs FIRST (overlaps writeback) ----
    float wreg[13];
    int   widx[13];
    #pragma unroll
    for (int k = 0; k < 13; ++k) {
        const int idx = tid + k * THREADS;
        widx[k] = idx;
        if (idx < 2 * Cc * Cc) {
            const int chn = idx / (Cc * Cc);
            const int rem = idx - chn * Cc * Cc;
            const int i = rem / Cc, j = rem - i * Cc;
            const float* Wp = chn ? Wr : W;
            wreg[k] = Wp[(size_t)i * (Dd + Cc) + Dd + j];
        }
    }
    float breg = 0.f;
    if (tid < 2 * Cc) breg = (tid < Cc) ? b[tid] : br[tid - Cc];

    // ---- accumulators -> smem bases[128][81] ----
    float* bases = smf + EPI_BASE_F;
    #pragma unroll
    for (int mt = 0; mt < 2; ++mt) {
        const int r = mw * 32 + mt * 16 + qr;
        #pragma unroll
        for (int t = 0; t < 5; ++t) {
            const int c = nw * 40 + t * 8 + qc * 2;
            bases[(r    ) * BROW + c    ] = acc[mt][t][0];
            bases[(r    ) * BROW + c + 1] = acc[mt][t][1];
            bases[(r + 8) * BROW + c    ] = acc[mt][t][2];
            bases[(r + 8) * BROW + c + 1] = acc[mt][t][3];
        }
    }

    float* wt = smf + EPI_WT_F;
    float* bb = smf + EPI_BB_F;
    #pragma unroll
    for (int k = 0; k < 13; ++k)
        if (widx[k] < 2 * Cc * Cc) wt[widx[k]] = wreg[k];
    if (tid < 2 * Cc) bb[tid] = breg;
    __syncthreads();

    // ---- sequential chains: 256 threads = 128 rows x 2 chains (split partials) ----
    {
        const int row = tid >> 1, chn = tid & 1;
        float* my        = bases + row * BROW + chn * Cc;
        const float* wtc = wt + chn * Cc * Cc;
        const float* bbc = bb + chn * Cc;
        float s[Cc];
        #pragma unroll
        for (int i = 0; i < Cc; ++i) {
            float x0 = my[i] + bbc[i];
            float x1 = 0.f;
            #pragma unroll
            for (int j = 0; j + 1 < i; j += 2) {
                x0 = fmaf(s[j],     wtc[i * Cc + j],     x0);
                x1 = fmaf(s[j + 1], wtc[i * Cc + j + 1], x1);
            }
            if (i & 1) x0 = fmaf(s[i - 1], wtc[i * Cc + i - 1], x0);
            const float x = x0 + x1;
            s[i] = 1.0f / (1.0f + __expf(-x));
            my[i] = s[i];
        }
    }
    __syncthreads();

    // ---- combine fwd + reversed rev, coalesced store ----
    #pragma unroll
    for (int it = 0; it < (RB * Cc) / THREADS; ++it) {   // 20
        const int idx = tid + it * THREADS;
        const int r = idx / Cc, c = idx - r * Cc;
        const float vf = bases[r * BROW + c];
        const float vr = bases[r * BROW + Cc + (Cc - 1 - c)];
        out[(size_t)(row0 + r) * Cc + c] = 0.5f * (vf + vr);
    }
}

extern "C" void kernel_launch(void* const* d_in, const int* in_sizes, int n_in,
                              void* d_out, int out_size) {
    const float* src = (const float*)d_in[0];
    // d_in[1] = attn_mask (unused)
    const float* W   = (const float*)d_in[2];
    const float* b   = (const float*)d_in[3];
    const float* Wr  = (const float*)d_in[4];
    const float* br  = (const float*)d_in[5];
    float* out = (float*)d_out;

    convert_w<<<(CT * Dd + 255) / 256, 256>>>(W, Wr);
    cudaFuncSetAttribute(bichain_r14,
                         cudaFuncAttributeMaxDynamicSharedMemorySize, SMEM_BYTES);
    bichain_r14<<<Bsz / RB, THREADS, SMEM_BYTES>>>(src, W, b, Wr, br, out);
}